// round 13
// baseline (speedup 1.0000x reference)
#include <cuda_runtime.h>
#include <cuda_fp16.h>
#include <math.h>
#include <stdint.h>

#define B     16
#define CIN   512
#define COUT  512
#define SD    512
#define H     32
#define W     32

#define CONV_SCALE 0.014731391274719736f   // 1/sqrt(512*9)
#define MOD_SCALE  0.044194173824159216f   // 1/sqrt(512)
#define SQRT2      1.4142135623730951f

#define KP        512                       // K per kk (fp16)
#define ITERS     36                        // 9 * (512/128)
#define TN        256
#define THREADS   256
#define STAGES    3
#define SUB_BYTES 16384                     // A only: 128 rows x 128B (64-K sub-stage)
#define STAGE_BYTES (2 * SUB_BYTES)         // 128-K stage
#define SMEM_DYN  (STAGES * STAGE_BYTES + 1024)

// ---------------- scratch ----------------
__device__ float g_s    [B * CIN];
__device__ float g_demod[B * COUT];
__device__ __half g_p3[(size_t)B * 34 * 34 * KP];      // [b][h'][w'][cin]
// B pre-fragmented: [kk][c64][kspair][n=512][t=4] uint4 (8 halves each)
__device__ uint4  g_w3f[(size_t)9 * 8 * 2 * 512 * 4];  // 4.7MB

// ---------------- PTX helpers (sm_80-level) ----------------
__device__ __forceinline__ uint32_t smem_u32(const void* p) {
    uint32_t a;
    asm("{ .reg .u64 t; cvta.to.shared.u64 t, %1; cvt.u32.u64 %0, t; }" : "=r"(a) : "l"(p));
    return a;
}
__device__ __forceinline__ void cp_async16(uint32_t dst, const void* src) {
    asm volatile("cp.async.cg.shared.global [%0], [%1], 16;" :: "r"(dst), "l"(src));
}
__device__ __forceinline__ void cp_commit() {
    asm volatile("cp.async.commit_group;" ::: "memory");
}
__device__ __forceinline__ void cp_wait2() {
    asm volatile("cp.async.wait_group 2;" ::: "memory");
}
__device__ __forceinline__ void ldsm4(uint32_t* r, uint32_t addr) {
    asm volatile("ldmatrix.sync.aligned.m8n8.x4.shared.b16 {%0,%1,%2,%3}, [%4];"
                 : "=r"(r[0]), "=r"(r[1]), "=r"(r[2]), "=r"(r[3]) : "r"(addr));
}
__device__ __forceinline__ void mma_f16v(float* d, const uint32_t* a, uint32_t b0, uint32_t b1) {
    asm volatile("mma.sync.aligned.m16n8k16.row.col.f32.f16.f16.f32 "
                 "{%0,%1,%2,%3}, {%4,%5,%6,%7}, {%8,%9}, {%0,%1,%2,%3};"
                 : "+f"(d[0]), "+f"(d[1]), "+f"(d[2]), "+f"(d[3])
                 : "r"(a[0]), "r"(a[1]), "r"(a[2]), "r"(a[3]), "r"(b0), "r"(b1));
}

// ---------------- kernel 1: style modulation ----------------
__global__ void k_style(const float* __restrict__ style,
                        const float* __restrict__ mod_w,
                        const float* __restrict__ mod_b) {
    int b = blockIdx.x;
    __shared__ float st[SD];
    for (int i = threadIdx.x; i < SD; i += 256) st[i] = style[b * SD + i];
    __syncthreads();
    int warp = threadIdx.x >> 5, lane = threadIdx.x & 31;
    for (int cin = warp; cin < CIN; cin += 8) {
        const float* mw = mod_w + cin * SD;
        float sum = 0.f;
        for (int d = lane; d < SD; d += 32) sum += mw[d] * st[d];
        #pragma unroll
        for (int o = 16; o; o >>= 1) sum += __shfl_xor_sync(0xFFFFFFFFu, sum, o);
        if (lane == 0)
            g_s[b * CIN + cin] = sum * MOD_SCALE + mod_b[cin];
    }
}

// ---------------- kernel 2: weights -> fragment layout + fused demod ----------------
__global__ void k_prep_w(const float* __restrict__ weight) {
    int cout = blockIdx.x;
    int tid = threadIdx.x;
    __shared__ float wrow[CIN * 9];
    __shared__ float wsq_s[CIN];

    const float* wp = weight + (size_t)cout * CIN * 9;
    for (int i = tid; i < CIN * 9; i += 256) wrow[i] = wp[i];
    __syncthreads();

    for (int c = tid; c < CIN; c += 256) {
        float ss = 0.f;
        #pragma unroll
        for (int kk = 0; kk < 9; kk++) {
            float w = wrow[c * 9 + kk] * CONV_SCALE;
            ss += w * w;
        }
        wsq_s[c] = ss;
    }
    __syncthreads();

    int warp = tid >> 5, lane = tid & 31;
    for (int b = warp; b < B; b += 8) {
        float sum = 0.f;
        for (int d = lane; d < CIN; d += 32) {
            float s = g_s[b * CIN + d];
            sum += wsq_s[d] * s * s;
        }
        #pragma unroll
        for (int o = 16; o; o >>= 1) sum += __shfl_xor_sync(0xFFFFFFFFu, sum, o);
        if (lane == 0) g_demod[b * COUT + cout] = rsqrtf(sum + 1e-8f);
    }

    // pack B fragments: 576 uint4 per cout = [kk(9)][c64(8)][kspair(2)][t(4)]
    for (int i = tid; i < 576; i += 256) {
        int t      = i & 3;
        int kspair = (i >> 2) & 1;
        int c64    = (i >> 3) & 7;
        int kk     = i >> 6;
        unsigned hh[8];
        #pragma unroll
        for (int j = 0; j < 8; j++) {
            int s = j >> 2, r = j & 3;
            int cin = c64 * 64 + (kspair * 2 + s) * 16 + t * 2 + ((r >> 1) * 8) + (r & 1);
            __half hv = __float2half_rn(wrow[cin * 9 + kk] * CONV_SCALE);
            hh[j] = (unsigned)__half_as_ushort(hv);
        }
        uint4 v;
        v.x = hh[0] | (hh[1] << 16);
        v.y = hh[2] | (hh[3] << 16);
        v.z = hh[4] | (hh[5] << 16);
        v.w = hh[6] | (hh[7] << 16);
        g_w3f[(((size_t)(kk * 8 + c64) * 2 + kspair) * 512 + cout) * 4 + t] = v;
    }
}

// ---------------- kernel 3: build P3 [b][h'][w'][cin] fp16 ----------------
__global__ void k_prep_x(const float* __restrict__ x) {
    int bid = blockIdx.x;
    int b  = bid / 34;
    int hp = bid % 34;
    int tid = threadIdx.x;
    size_t rowbase = ((size_t)(b * 34 + hp) * 34) * KP;

    if (hp == 0 || hp == 33) {
        uint4* dst = (uint4*)(g_p3 + rowbase);
        uint4 z = {0, 0, 0, 0};
        for (int i = tid; i < 34 * KP * 2 / 16; i += 256) dst[i] = z;
        return;
    }
    int h = hp - 1;
    __shared__ float xs[256][33];

    for (int pass = 0; pass < 2; pass++) {
        int cp = pass * 256;
        __syncthreads();
        for (int i = tid; i < 256 * 32; i += 256) {
            int ci = i >> 5, w = i & 31;
            float s = g_s[b * CIN + cp + ci];
            xs[ci][w] = x[(((size_t)b * CIN + cp + ci) * H + h) * W + w] * s;
        }
        __syncthreads();
        for (int wp = 0; wp < 34; wp++) {
            int w = wp - 1;
            __half* dst = g_p3 + rowbase + (size_t)wp * KP + pass * 256;
            if (w < 0 || w >= 32) {
                for (int j = tid; j < 256; j += 256) dst[j] = __float2half_rn(0.f);
            } else {
                for (int j = tid; j < 256; j += 256)
                    dst[j] = __float2half_rn(xs[j][w]);
            }
        }
    }
}

// ---------------- kernel 4: mma.sync GEMM, 8 warps, 64x64 warp tiles ----------------
// grid 256: nt = bx&1, mt = bx>>1. CTA tile 128x256, 256 threads, 3-stage A ring.
// warp_m = wid&1 (64 M rows), warp_n = wid>>1 (64 couts). 128 acc/thread.
__global__ __launch_bounds__(THREADS, 1) void k_gemm(
    const float* __restrict__ noise,
    const float* __restrict__ noise_weight,
    const float* __restrict__ act_bias,
    float* __restrict__ out)
{
    extern __shared__ char dyn_smem[];
    const uint32_t base = (smem_u32(dyn_smem) + 1023u) & ~1023u;

    const int tid  = threadIdx.x;
    const int lane = tid & 31;
    const int wid  = tid >> 5;
    const int nt = blockIdx.x & 1;
    const int mt = blockIdx.x >> 1;
    const int b  = mt >> 3;
    const int h0 = (mt & 7) * 4;
    const int cout0 = nt * TN;

    // ---- A loader state (per sub-stage: 4 chunks of 16B per thread) ----
    const int rA  = tid >> 1;                 // A row 0..127
    const int ccA = 4 * (tid & 1);            // chunks ccA..ccA+3
    const int dhA = rA >> 5, wA = rA & 31;
    uint32_t dstA[4];
    #pragma unroll
    for (int j = 0; j < 4; j++)
        dstA[j] = rA * 128 + (((ccA + j) ^ (rA & 7)) << 4);

    // ---- compute-phase per-thread constants ----
    const int sub = lane >> 3, l7 = lane & 7;
    const int warp_m = wid & 1, warp_n = wid >> 1;
    const uint32_t aRowBase = (uint32_t)(warp_m * 64 + (sub & 1) * 8 + l7) * 128;
    const int aHalf = sub >> 1;
    // B fragment LDG base (uint4 index): n-tile j at +j*32
    const uint32_t lb = (uint32_t)(cout0 + warp_n * 64) * 4 + lane;

    float acc[4][8][4];
    #pragma unroll
    for (int mi = 0; mi < 4; mi++)
        #pragma unroll
        for (int nj = 0; nj < 8; nj++)
            #pragma unroll
            for (int q = 0; q < 4; q++) acc[mi][nj][q] = 0.f;

    // ---- A stage loader: K-chunk 128 = two 64-K sub-stages ----
    auto load_stage = [&](int st, int chunk) {
        int kk = chunk >> 2;
        int ky = kk / 3, kx = kk - ky * 3;
        int k0 = (chunk & 3) * 128;
        uint32_t sb = base + st * STAGE_BYTES;
        const __half* srcA0 = g_p3
            + ((size_t)((b * 34 + h0 + dhA + ky) * 34) + (wA + kx)) * KP + k0 + ccA * 8;
        #pragma unroll
        for (int sc = 0; sc < 2; sc++) {
            uint32_t sbs = sb + sc * SUB_BYTES;
            const __half* srcA = srcA0 + sc * 64;
            #pragma unroll
            for (int j = 0; j < 4; j++) cp_async16(sbs + dstA[j], srcA + j * 8);
        }
    };

    // prologue: stages 0,1 <- chunks 0,1
    load_stage(0, 0); cp_commit();
    load_stage(1, 1); cp_commit();

    int st = 0;
    for (int it = 0; it < ITERS; ++it) {
        if (it) __syncthreads();
        if (it + 2 < ITERS) load_stage((st + 2) % STAGES, it + 2);
        cp_commit();
        cp_wait2();
        __syncthreads();

        const int ckk   = it >> 2;
        const int cbase = (it & 3) * 2;

        uint32_t sb = base + st * STAGE_BYTES;
        #pragma unroll
        for (int sc = 0; sc < 2; sc++) {
            const int c64 = cbase + sc;
            const uint4* bp = g_w3f + (size_t)((ckk * 8 + c64) * 2) * 2048 + lb;
            uint32_t sbs = sb + sc * SUB_BYTES;
            #pragma unroll
            for (int kp = 0; kp < 2; kp++) {
                uint4 bq[8];
                #pragma unroll
                for (int j = 0; j < 8; j++)
                    bq[j] = bp[kp * 2048 + j * 32];
                #pragma unroll
                for (int s = 0; s < 2; s++) {
                    int ks = kp * 2 + s;
                    #pragma unroll
                    for (int mi = 0; mi < 4; mi++) {
                        uint32_t ar[4];
                        ldsm4(ar, sbs + aRowBase + mi * 2048 + (((ks * 2 + aHalf) ^ l7) << 4));
                        #pragma unroll
                        for (int j = 0; j < 8; j++) {
                            uint32_t b0 = s ? bq[j].z : bq[j].x;
                            uint32_t b1 = s ? bq[j].w : bq[j].y;
                            mma_f16v(acc[mi][j], ar, b0, b1);
                        }
                    }
                }
            }
        }
        if (++st == STAGES) st = 0;
    }

    // ---- epilogue ----
    const int grp = lane >> 2, qt = lane & 3;
    const float nwv = noise_weight[0];
    #pragma unroll
    for (int mi = 0; mi < 4; mi++) {
        #pragma unroll
        for (int rr = 0; rr < 2; rr++) {
            int ml = warp_m * 64 + mi * 16 + grp + rr * 8;
            int h  = h0 + (ml >> 5);
            int w  = ml & 31;
            float nz = noise[(b * H + h) * W + w] * nwv;
            #pragma unroll
            for (int nj = 0; nj < 8; nj++) {
                int cout = cout0 + warp_n * 64 + nj * 8 + qt * 2;
                #pragma unroll
                for (int cc = 0; cc < 2; cc++) {
                    float v = acc[mi][nj][rr * 2 + cc] * g_demod[b * COUT + cout + cc]
                              + nz + act_bias[cout + cc];
                    v = (v > 0.f) ? v : 0.2f * v;
                    out[(((size_t)b * COUT + cout + cc) * H + h) * W + w] = v * SQRT2;
                }
            }
        }
    }
}

// ---------------- launch: exactly 4 kernels ----------------
extern "C" void kernel_launch(void* const* d_in, const int* in_sizes, int n_in,
                              void* d_out, int out_size) {
    const float* x       = (const float*)d_in[0];
    const float* style   = (const float*)d_in[1];
    const float* noise   = (const float*)d_in[2];
    const float* weight  = (const float*)d_in[3];
    const float* mod_w   = (const float*)d_in[4];
    const float* mod_b   = (const float*)d_in[5];
    const float* nw      = (const float*)d_in[6];
    const float* act_b   = (const float*)d_in[7];
    float* out = (float*)d_out;

    cudaFuncSetAttribute(k_gemm, cudaFuncAttributeMaxDynamicSharedMemorySize, SMEM_DYN);

    k_style<<<B, 256>>>(style, mod_w, mod_b);
    k_prep_w<<<COUT, 256>>>(weight);
    k_prep_x<<<B * 34, 256>>>(x);
    k_gemm<<<256, THREADS, SMEM_DYN>>>(noise, nw, act_b, out);
}

// round 14
// speedup vs baseline: 1.0444x; 1.0444x over previous
#include <cuda_runtime.h>
#include <cuda_fp16.h>
#include <math.h>
#include <stdint.h>

#define B     16
#define CIN   512
#define COUT  512
#define SD    512
#define H     32
#define W     32

#define CONV_SCALE 0.014731391274719736f   // 1/sqrt(512*9)
#define MOD_SCALE  0.044194173824159216f   // 1/sqrt(512)
#define SQRT2      1.4142135623730951f

#define KP        512                       // K per kk (fp16)
#define ITERS     36                        // 9 * (512/128)
#define TN        256
#define THREADS   512
#define STAGES    4
#define SUB_BYTES 16384                     // A only: 128 rows x 128B (64-K sub-stage)
#define STAGE_BYTES (2 * SUB_BYTES)         // 128-K stage
#define SMEM_DYN  (STAGES * STAGE_BYTES + 1024)

// ---------------- scratch ----------------
__device__ float g_s    [B * CIN];
__device__ float g_demod[B * COUT];
__device__ __half g_p3[(size_t)B * 34 * 34 * KP];      // [b][h'][w'][cin]
// B pre-fragmented: [kk][c64][kspair][n=512][t=4] uint4 (8 halves each)
__device__ uint4  g_w3f[(size_t)9 * 8 * 2 * 512 * 4];  // 4.7MB

// ---------------- PTX helpers (sm_80-level) ----------------
__device__ __forceinline__ uint32_t smem_u32(const void* p) {
    uint32_t a;
    asm("{ .reg .u64 t; cvta.to.shared.u64 t, %1; cvt.u32.u64 %0, t; }" : "=r"(a) : "l"(p));
    return a;
}
__device__ __forceinline__ void cp_async16(uint32_t dst, const void* src) {
    asm volatile("cp.async.cg.shared.global [%0], [%1], 16;" :: "r"(dst), "l"(src));
}
__device__ __forceinline__ void cp_commit() {
    asm volatile("cp.async.commit_group;" ::: "memory");
}
__device__ __forceinline__ void cp_wait2() {
    asm volatile("cp.async.wait_group 2;" ::: "memory");
}
__device__ __forceinline__ void ldsm4(uint32_t* r, uint32_t addr) {
    asm volatile("ldmatrix.sync.aligned.m8n8.x4.shared.b16 {%0,%1,%2,%3}, [%4];"
                 : "=r"(r[0]), "=r"(r[1]), "=r"(r[2]), "=r"(r[3]) : "r"(addr));
}
__device__ __forceinline__ void mma_f16v(float* d, const uint32_t* a, uint32_t b0, uint32_t b1) {
    asm volatile("mma.sync.aligned.m16n8k16.row.col.f32.f16.f16.f32 "
                 "{%0,%1,%2,%3}, {%4,%5,%6,%7}, {%8,%9}, {%0,%1,%2,%3};"
                 : "+f"(d[0]), "+f"(d[1]), "+f"(d[2]), "+f"(d[3])
                 : "r"(a[0]), "r"(a[1]), "r"(a[2]), "r"(a[3]), "r"(b0), "r"(b1));
}

// ---------------- kernel 1: style modulation ----------------
__global__ void k_style(const float* __restrict__ style,
                        const float* __restrict__ mod_w,
                        const float* __restrict__ mod_b) {
    int b = blockIdx.x;
    __shared__ float st[SD];
    for (int i = threadIdx.x; i < SD; i += 256) st[i] = style[b * SD + i];
    __syncthreads();
    int warp = threadIdx.x >> 5, lane = threadIdx.x & 31;
    for (int cin = warp; cin < CIN; cin += 8) {
        const float* mw = mod_w + cin * SD;
        float sum = 0.f;
        for (int d = lane; d < SD; d += 32) sum += mw[d] * st[d];
        #pragma unroll
        for (int o = 16; o; o >>= 1) sum += __shfl_xor_sync(0xFFFFFFFFu, sum, o);
        if (lane == 0)
            g_s[b * CIN + cin] = sum * MOD_SCALE + mod_b[cin];
    }
}

// ---------------- kernel 2: weights -> fragment layout + fused demod ----------------
__global__ void k_prep_w(const float* __restrict__ weight) {
    int cout = blockIdx.x;
    int tid = threadIdx.x;
    __shared__ float wrow[CIN * 9];
    __shared__ float wsq_s[CIN];

    const float* wp = weight + (size_t)cout * CIN * 9;
    for (int i = tid; i < CIN * 9; i += 256) wrow[i] = wp[i];
    __syncthreads();

    for (int c = tid; c < CIN; c += 256) {
        float ss = 0.f;
        #pragma unroll
        for (int kk = 0; kk < 9; kk++) {
            float w = wrow[c * 9 + kk] * CONV_SCALE;
            ss += w * w;
        }
        wsq_s[c] = ss;
    }
    __syncthreads();

    int warp = tid >> 5, lane = tid & 31;
    for (int b = warp; b < B; b += 8) {
        float sum = 0.f;
        for (int d = lane; d < CIN; d += 32) {
            float s = g_s[b * CIN + d];
            sum += wsq_s[d] * s * s;
        }
        #pragma unroll
        for (int o = 16; o; o >>= 1) sum += __shfl_xor_sync(0xFFFFFFFFu, sum, o);
        if (lane == 0) g_demod[b * COUT + cout] = rsqrtf(sum + 1e-8f);
    }

    // pack B fragments: 576 uint4 per cout = [kk(9)][c64(8)][kspair(2)][t(4)]
    for (int i = tid; i < 576; i += 256) {
        int t      = i & 3;
        int kspair = (i >> 2) & 1;
        int c64    = (i >> 3) & 7;
        int kk     = i >> 6;
        unsigned hh[8];
        #pragma unroll
        for (int j = 0; j < 8; j++) {
            int s = j >> 2, r = j & 3;
            int cin = c64 * 64 + (kspair * 2 + s) * 16 + t * 2 + ((r >> 1) * 8) + (r & 1);
            __half hv = __float2half_rn(wrow[cin * 9 + kk] * CONV_SCALE);
            hh[j] = (unsigned)__half_as_ushort(hv);
        }
        uint4 v;
        v.x = hh[0] | (hh[1] << 16);
        v.y = hh[2] | (hh[3] << 16);
        v.z = hh[4] | (hh[5] << 16);
        v.w = hh[6] | (hh[7] << 16);
        g_w3f[(((size_t)(kk * 8 + c64) * 2 + kspair) * 512 + cout) * 4 + t] = v;
    }
}

// ---------------- kernel 3: build P3 [b][h'][w'][cin] fp16 ----------------
__global__ void k_prep_x(const float* __restrict__ x) {
    int bid = blockIdx.x;
    int b  = bid / 34;
    int hp = bid % 34;
    int tid = threadIdx.x;
    size_t rowbase = ((size_t)(b * 34 + hp) * 34) * KP;

    if (hp == 0 || hp == 33) {
        uint4* dst = (uint4*)(g_p3 + rowbase);
        uint4 z = {0, 0, 0, 0};
        for (int i = tid; i < 34 * KP * 2 / 16; i += 256) dst[i] = z;
        return;
    }
    int h = hp - 1;
    __shared__ float xs[256][33];

    for (int pass = 0; pass < 2; pass++) {
        int cp = pass * 256;
        __syncthreads();
        for (int i = tid; i < 256 * 32; i += 256) {
            int ci = i >> 5, w = i & 31;
            float s = g_s[b * CIN + cp + ci];
            xs[ci][w] = x[(((size_t)b * CIN + cp + ci) * H + h) * W + w] * s;
        }
        __syncthreads();
        for (int wp = 0; wp < 34; wp++) {
            int w = wp - 1;
            __half* dst = g_p3 + rowbase + (size_t)wp * KP + pass * 256;
            if (w < 0 || w >= 32) {
                for (int j = tid; j < 256; j += 256) dst[j] = __float2half_rn(0.f);
            } else {
                for (int j = tid; j < 256; j += 256)
                    dst[j] = __float2half_rn(xs[j][w]);
            }
        }
    }
}

// ---------------- kernel 4: mma.sync GEMM, A via smem/ldsm, B via LDG.128 frags ----------------
// grid 256: nt = bx&1, mt = bx>>1. CTA tile 128x256, 512 threads (16 warps, 64x32 warp tile).
// 4-stage A ring, prefetch distance 2, ONE __syncthreads per iteration.
__global__ __launch_bounds__(THREADS, 1) void k_gemm(
    const float* __restrict__ noise,
    const float* __restrict__ noise_weight,
    const float* __restrict__ act_bias,
    float* __restrict__ out)
{
    extern __shared__ char dyn_smem[];
    const uint32_t base = (smem_u32(dyn_smem) + 1023u) & ~1023u;

    const int tid  = threadIdx.x;
    const int lane = tid & 31;
    const int wid  = tid >> 5;
    const int nt = blockIdx.x & 1;
    const int mt = blockIdx.x >> 1;
    const int b  = mt >> 3;
    const int h0 = (mt & 7) * 4;
    const int cout0 = nt * TN;

    // ---- A loader state (per sub-stage: 2 chunks of 16B per thread) ----
    const int rA  = tid >> 2;                 // A row 0..127
    const int ccA = 2 * (tid & 3);            // chunks ccA, ccA+1
    const int dhA = rA >> 5, wA = rA & 31;
    uint32_t dstA[2];
    #pragma unroll
    for (int j = 0; j < 2; j++)
        dstA[j] = rA * 128 + (((ccA + j) ^ (rA & 7)) << 4);

    // ---- compute-phase per-thread constants ----
    const int sub = lane >> 3, l7 = lane & 7;
    const int warp_m = wid & 1, warp_n = wid >> 1;
    const uint32_t aRowBase = (uint32_t)(warp_m * 64 + (sub & 1) * 8 + l7) * 128;
    const int aHalf = sub >> 1;
    const uint32_t lb = (uint32_t)(cout0 + warp_n * 32) * 4 + lane;

    float acc[4][4][4];
    #pragma unroll
    for (int mi = 0; mi < 4; mi++)
        #pragma unroll
        for (int nj = 0; nj < 4; nj++)
            #pragma unroll
            for (int q = 0; q < 4; q++) acc[mi][nj][q] = 0.f;

    // ---- A stage loader: 128-K chunk = two 64-K sub-stages ----
    auto load_stage = [&](int st, int chunk) {
        int kk = chunk >> 2;
        int ky = kk / 3, kx = kk - ky * 3;
        int k0 = (chunk & 3) * 128;
        uint32_t sb = base + st * STAGE_BYTES;
        const __half* srcA0 = g_p3
            + ((size_t)((b * 34 + h0 + dhA + ky) * 34) + (wA + kx)) * KP + k0 + ccA * 8;
        #pragma unroll
        for (int sc = 0; sc < 2; sc++) {
            uint32_t sbs = sb + sc * SUB_BYTES;
            const __half* srcA = srcA0 + sc * 64;
            cp_async16(sbs + dstA[0], srcA);
            cp_async16(sbs + dstA[1], srcA + 8);
        }
    };

    // prologue: stages 0,1 <- chunks 0,1
    load_stage(0, 0); cp_commit();
    load_stage(1, 1); cp_commit();

    int st = 0;
    for (int it = 0; it < ITERS; ++it) {
        // prefetch chunk it+2 into stage (st+2)%4; last readers of that stage
        // ran compute(it-2), ordered by the sync at iter it-1.
        if (it + 2 < ITERS) load_stage((st + 2) & 3, it + 2);
        cp_commit();
        cp_wait2();          // stage `it` data complete (2 newest groups may be in flight)
        __syncthreads();     // all threads' waits passed -> data visible to all

        const int ckk   = it >> 2;
        const int cbase = (it & 3) * 2;

        uint32_t sb = base + st * STAGE_BYTES;
        #pragma unroll
        for (int sc = 0; sc < 2; sc++) {
            const int c64 = cbase + sc;
            const uint4* bp = g_w3f + (size_t)((ckk * 8 + c64) * 2) * 2048 + lb;
            uint4 bq[2][2][2];   // [kspair][p][q]
            #pragma unroll
            for (int kp = 0; kp < 2; kp++)
                #pragma unroll
                for (int p = 0; p < 2; p++)
                    #pragma unroll
                    for (int q = 0; q < 2; q++)
                        bq[kp][p][q] = bp[kp * 2048 + p * 64 + q * 32];

            uint32_t sbs = sb + sc * SUB_BYTES;
            #pragma unroll
            for (int kp = 0; kp < 2; kp++) {
                #pragma unroll
                for (int s = 0; s < 2; s++) {
                    int ks = kp * 2 + s;
                    #pragma unroll
                    for (int mi = 0; mi < 4; mi++) {
                        uint32_t ar[4];
                        ldsm4(ar, sbs + aRowBase + mi * 2048 + (((ks * 2 + aHalf) ^ l7) << 4));
                        #pragma unroll
                        for (int p = 0; p < 2; p++)
                            #pragma unroll
                            for (int q = 0; q < 2; q++) {
                                uint32_t b0 = s ? bq[kp][p][q].z : bq[kp][p][q].x;
                                uint32_t b1 = s ? bq[kp][p][q].w : bq[kp][p][q].y;
                                mma_f16v(acc[mi][p * 2 + q], ar, b0, b1);
                            }
                    }
                }
            }
        }
        st = (st + 1) & 3;
    }

    // ---- epilogue ----
    const int grp = lane >> 2, qt = lane & 3;
    const float nwv = noise_weight[0];
    #pragma unroll
    for (int mi = 0; mi < 4; mi++) {
        #pragma unroll
        for (int rr = 0; rr < 2; rr++) {
            int ml = warp_m * 64 + mi * 16 + grp + rr * 8;
            int h  = h0 + (ml >> 5);
            int w  = ml & 31;
            float nz = noise[(b * H + h) * W + w] * nwv;
            #pragma unroll
            for (int nj = 0; nj < 4; nj++) {
                int cout = cout0 + warp_n * 32 + nj * 8 + qt * 2;
                #pragma unroll
                for (int cc = 0; cc < 2; cc++) {
                    float v = acc[mi][nj][rr * 2 + cc] * g_demod[b * COUT + cout + cc]
                              + nz + act_bias[cout + cc];
                    v = (v > 0.f) ? v : 0.2f * v;
                    out[(((size_t)b * COUT + cout + cc) * H + h) * W + w] = v * SQRT2;
                }
            }
        }
    }
}

// ---------------- launch: exactly 4 kernels ----------------
extern "C" void kernel_launch(void* const* d_in, const int* in_sizes, int n_in,
                              void* d_out, int out_size) {
    const float* x       = (const float*)d_in[0];
    const float* style   = (const float*)d_in[1];
    const float* noise   = (const float*)d_in[2];
    const float* weight  = (const float*)d_in[3];
    const float* mod_w   = (const float*)d_in[4];
    const float* mod_b   = (const float*)d_in[5];
    const float* nw      = (const float*)d_in[6];
    const float* act_b   = (const float*)d_in[7];
    float* out = (float*)d_out;

    cudaFuncSetAttribute(k_gemm, cudaFuncAttributeMaxDynamicSharedMemorySize, SMEM_DYN);

    k_style<<<B, 256>>>(style, mod_w, mod_b);
    k_prep_w<<<COUT, 256>>>(weight);
    k_prep_x<<<B * 34, 256>>>(x);
    k_gemm<<<256, THREADS, SMEM_DYN>>>(noise, nw, act_b, out);
}